// round 1
// baseline (speedup 1.0000x reference)
#include <cuda_runtime.h>
#include <math.h>

// DCT_18769007084406
// x[32,3,512,512] fp32 -> out[32,192,64,64] fp32
// Fused: YCbCr 1x1 conv + separable 8x8 block DCT + closed-form 32x affine norm.

#define NTHREADS 256
#define PITCH 68                      // floats per j-row of G (68 % 32 == 4 -> conflict-free)
#define G_FLOATS (24 * 8 * PITCH)     // 13056 floats = 52224 bytes
#define SMEM_FLOATS (G_FLOATS + 64 + 2 * 192)
#define SMEM_BYTES (SMEM_FLOATS * 4)  // 54016 bytes

__global__ void __launch_bounds__(NTHREADS)
dct_fused_kernel(const float* __restrict__ x,
                 const float* __restrict__ max_,
                 const float* __restrict__ min_,
                 const float* __restrict__ ycw,
                 float* __restrict__ out)
{
    extern __shared__ float sm[];
    float*  G   = sm;                       // [(cu*8 + j)*PITCH + bw]
    float*  bas = sm + G_FLOATS;            // bas[u*8 + i]
    float2* aff = (float2*)(sm + G_FLOATS + 64);  // [192] {scale, bias}

    const int t = threadIdx.x;
    const int r = blockIdx.x;   // block-row 0..63
    const int b = blockIdx.y;   // batch   0..31

    // --- DCT basis (double precision, matches numpy construction) ---
    if (t < 64) {
        int u = t >> 3, i = t & 7;
        double c = (u == 0) ? sqrt(0.125) : 0.5;
        bas[t] = (float)(c * cos(M_PI * (double)u * (double)(2 * i + 1) / 16.0));
    }
    // --- closed-form affine for the 32x repeated (t - min)/d ---
    if (t < 192) {
        float mx = max_[b * 192 + t];
        float mn = min_[b * 192 + t];
        float d  = mx - mn + 1e-6f;
        float rr  = 1.0f / d;
        float r2  = rr * rr;
        float r4  = r2 * r2;
        float r8  = r4 * r4;
        float r16 = r8 * r8;
        float r32 = r16 * r16;
        float bias = -mn * (rr * (1.0f - r32) / (1.0f - rr));
        aff[t] = make_float2(r32, bias);
    }

    // YCbCr weights into registers (uniform, L1-cached)
    const float w00 = ycw[0], w01 = ycw[1], w02 = ycw[2];
    const float w10 = ycw[3], w11 = ycw[4], w12 = ycw[5];
    const float w20 = ycw[6], w21 = ycw[7], w22 = ycw[8];

    __syncthreads();

    // ---------------- Stage A: vertical DCT (input read once from GMEM) ----
    // Thread handles columns t and t+256 of the 8x512 strip.
    const float* xb = x + ((size_t)b * 3 * 512 + (size_t)r * 8) * 512;

    #pragma unroll
    for (int pass = 0; pass < 2; ++pass) {
        const int col = t + pass * 256;
        float acc[24];
        #pragma unroll
        for (int k = 0; k < 24; ++k) acc[k] = 0.0f;

        #pragma unroll
        for (int i = 0; i < 8; ++i) {
            const float rv = __ldg(xb +                   i * 512 + col);
            const float gv = __ldg(xb + 512 * 512 +       i * 512 + col);
            const float bv = __ldg(xb + 2 * 512 * 512 +   i * 512 + col);
            const float y  = w00 * rv + w01 * gv + w02 * bv;
            const float cb = w10 * rv + w11 * gv + w12 * bv;
            const float cr = w20 * rv + w21 * gv + w22 * bv;
            #pragma unroll
            for (int u = 0; u < 8; ++u) {
                const float bu = bas[u * 8 + i];
                acc[u]      = fmaf(bu, y,  acc[u]);
                acc[8 + u]  = fmaf(bu, cb, acc[8 + u]);
                acc[16 + u] = fmaf(bu, cr, acc[16 + u]);
            }
        }
        const int j  = col & 7;
        const int bw = col >> 3;
        #pragma unroll
        for (int cu = 0; cu < 24; ++cu)
            G[(cu * 8 + j) * PITCH + bw] = acc[cu];
    }

    __syncthreads();

    // ---------------- Stage B: horizontal DCT + affine + coalesced store ---
    const int bw  = t & 63;
    const int cu0 = t >> 6;   // 0..3
    const size_t outb = (size_t)b * 192 * 4096 + (size_t)r * 64 + bw;

    #pragma unroll
    for (int q = 0; q < 6; ++q) {
        const int cu = cu0 + q * 4;          // c*8 + u
        float vals[8];
        #pragma unroll
        for (int j = 0; j < 8; ++j)
            vals[j] = G[(cu * 8 + j) * PITCH + bw];

        const int kbase = (cu >> 3) * 64 + (cu & 7) * 8;  // c*64 + u*8
        #pragma unroll
        for (int v = 0; v < 8; ++v) {
            float o = 0.0f;
            #pragma unroll
            for (int j = 0; j < 8; ++j)
                o = fmaf(bas[v * 8 + j], vals[j], o);
            const float2 sb = aff[kbase + v];
            out[outb + (size_t)(kbase + v) * 4096] = fmaf(o, sb.x, sb.y);
        }
    }
}

extern "C" void kernel_launch(void* const* d_in, const int* in_sizes, int n_in,
                              void* d_out, int out_size)
{
    const float* x    = (const float*)d_in[0];
    const float* max_ = (const float*)d_in[1];
    const float* min_ = (const float*)d_in[2];
    const float* ycw  = (const float*)d_in[3];
    // d_in[4] = dct_w: unused (basis computed analytically, identical values)
    float* out = (float*)d_out;

    cudaFuncSetAttribute(dct_fused_kernel,
                         cudaFuncAttributeMaxDynamicSharedMemorySize, SMEM_BYTES);

    dim3 grid(64, 32);  // (block-row, batch)
    dct_fused_kernel<<<grid, NTHREADS, SMEM_BYTES>>>(x, max_, min_, ycw, out);
}

// round 2
// speedup vs baseline: 1.4085x; 1.4085x over previous
#include <cuda_runtime.h>

// DCT_18769007084406 — fused YCbCr + separable 8x8 block DCT + closed-form affine.
// x[32,3,512,512] fp32 -> out[32,192,64,64] fp32
// CTA = one 8x256 strip (half a block-row). Basis baked as compile-time immediates.

#define NT 256
#define PITCH 36                      // 36 % 32 == 4 -> conflict-free both stages
#define GF (24 * 8 * PITCH)           // 6912 floats = 27648 B

// DCT-II basis b[u][i] = c(u)*cos(pi*u*(2i+1)/16), c(0)=sqrt(1/8), else 0.5.
// Values exact to double precision (matches numpy fp64 -> fp32 cast).
static __device__ constexpr float BAS[8][8] = {
  { 0.35355339059327373f,  0.35355339059327373f,  0.35355339059327373f,  0.35355339059327373f,
    0.35355339059327373f,  0.35355339059327373f,  0.35355339059327373f,  0.35355339059327373f },
  { 0.49039264020161522f,  0.41573480615127262f,  0.27778511650980114f,  0.09754516100806417f,
   -0.09754516100806417f, -0.27778511650980114f, -0.41573480615127262f, -0.49039264020161522f },
  { 0.46193976625564337f,  0.19134171618254492f, -0.19134171618254492f, -0.46193976625564337f,
   -0.46193976625564337f, -0.19134171618254492f,  0.19134171618254492f,  0.46193976625564337f },
  { 0.41573480615127262f, -0.09754516100806417f, -0.49039264020161522f, -0.27778511650980114f,
    0.27778511650980114f,  0.49039264020161522f,  0.09754516100806417f, -0.41573480615127262f },
  { 0.35355339059327373f, -0.35355339059327373f, -0.35355339059327373f,  0.35355339059327373f,
    0.35355339059327373f, -0.35355339059327373f, -0.35355339059327373f,  0.35355339059327373f },
  { 0.27778511650980114f, -0.49039264020161522f,  0.09754516100806417f,  0.41573480615127262f,
   -0.41573480615127262f, -0.09754516100806417f,  0.49039264020161522f, -0.27778511650980114f },
  { 0.19134171618254492f, -0.46193976625564337f,  0.46193976625564337f, -0.19134171618254492f,
   -0.19134171618254492f,  0.46193976625564337f, -0.46193976625564337f,  0.19134171618254492f },
  { 0.09754516100806417f, -0.27778511650980114f,  0.41573480615127262f, -0.49039264020161522f,
    0.49039264020161522f, -0.41573480615127262f,  0.27778511650980114f, -0.09754516100806417f }
};

__global__ void __launch_bounds__(NT, 4)
dct_fused_kernel(const float* __restrict__ x,
                 const float* __restrict__ max_,
                 const float* __restrict__ min_,
                 const float* __restrict__ ycw,
                 float* __restrict__ out)
{
    __shared__ float  G[GF];          // [(cu*8 + j)*PITCH + bw]
    __shared__ float2 aff[192];       // {scale, bias} per k

    const int t    = threadIdx.x;
    const int bx   = blockIdx.x;      // 0..127
    const int r    = bx >> 1;         // block-row 0..63
    const int half = bx & 1;          // left/right 256-col half
    const int b    = blockIdx.y;      // batch

    // closed-form of 32x repeated t <- (t - min)/d
    if (t < 192) {
        const float mx = max_[b * 192 + t];
        const float mn = min_[b * 192 + t];
        const float d  = mx - mn + 1e-6f;
        const float rr = 1.0f / d;
        float r2 = rr * rr, r4 = r2 * r2, r8 = r4 * r4, r16 = r8 * r8;
        const float r32 = r16 * r16;
        aff[t] = make_float2(r32, -mn * (rr * (1.0f - r32) / (1.0f - rr)));
    }

    const float w00 = ycw[0], w01 = ycw[1], w02 = ycw[2];
    const float w10 = ycw[3], w11 = ycw[4], w12 = ycw[5];
    const float w20 = ycw[6], w21 = ycw[7], w22 = ycw[8];

    // ---------------- Stage A: front-batched loads + vertical DCT ----------
    const float* xb = x + ((size_t)b * 3 * 512 + (size_t)r * 8) * 512 + half * 256;

    float v[24];
    #pragma unroll
    for (int c = 0; c < 3; ++c)
        #pragma unroll
        for (int i = 0; i < 8; ++i)
            v[c * 8 + i] = __ldg(xb + c * 262144 + i * 512 + t);

    float acc[24];
    #pragma unroll
    for (int k = 0; k < 24; ++k) acc[k] = 0.0f;

    #pragma unroll
    for (int i = 0; i < 8; ++i) {
        const float rv = v[i], gv = v[8 + i], bv = v[16 + i];
        const float y  = fmaf(w00, rv, fmaf(w01, gv, w02 * bv));
        const float cb = fmaf(w10, rv, fmaf(w11, gv, w12 * bv));
        const float cr = fmaf(w20, rv, fmaf(w21, gv, w22 * bv));
        #pragma unroll
        for (int u = 0; u < 8; ++u) {
            acc[u]      = fmaf(BAS[u][i], y,  acc[u]);
            acc[8 + u]  = fmaf(BAS[u][i], cb, acc[8 + u]);
            acc[16 + u] = fmaf(BAS[u][i], cr, acc[16 + u]);
        }
    }

    const int j  = t & 7;
    const int bw = t >> 3;            // 0..31
    #pragma unroll
    for (int cu = 0; cu < 24; ++cu)
        G[(cu * 8 + j) * PITCH + bw] = acc[cu];

    __syncthreads();

    // ---------------- Stage B: horizontal DCT + affine + coalesced store ---
    const int bwB = t & 31;
    const int cu0 = t >> 5;           // 0..7
    const size_t outb = (size_t)b * 192 * 4096 + (size_t)r * 64 + half * 32 + bwB;

    #pragma unroll
    for (int q = 0; q < 3; ++q) {
        const int cu = cu0 + q * 8;   // 0..23 == c*8 + u
        float vals[8];
        #pragma unroll
        for (int jj = 0; jj < 8; ++jj)
            vals[jj] = G[(cu * 8 + jj) * PITCH + bwB];

        const int kbase = cu * 8;     // k = c*64 + u*8 + v == cu*8 + v
        #pragma unroll
        for (int vv = 0; vv < 8; ++vv) {
            float o = vals[0] * BAS[vv][0];
            #pragma unroll
            for (int jj = 1; jj < 8; ++jj)
                o = fmaf(BAS[vv][jj], vals[jj], o);
            const float2 sb = aff[kbase + vv];
            out[outb + (size_t)(kbase + vv) * 4096] = fmaf(o, sb.x, sb.y);
        }
    }
}

extern "C" void kernel_launch(void* const* d_in, const int* in_sizes, int n_in,
                              void* d_out, int out_size)
{
    const float* x    = (const float*)d_in[0];
    const float* max_ = (const float*)d_in[1];
    const float* min_ = (const float*)d_in[2];
    const float* ycw  = (const float*)d_in[3];
    // d_in[4] = dct_w unused (basis is compile-time constant, identical values)
    float* out = (float*)d_out;

    dim3 grid(128, 32);               // (block-row halves, batch)
    dct_fused_kernel<<<grid, NT>>>(x, max_, min_, ycw, out);
}

// round 3
// speedup vs baseline: 1.4926x; 1.0597x over previous
#include <cuda_runtime.h>

// DCT_18769007084406 — per-channel separable 8x8 DCT, YCbCr mix commuted to the
// epilogue (linearity), butterfly DCT, closed-form 32x affine.
// x[32,3,512,512] fp32 -> out[32,192,64,64] fp32

#define NT 256
#define PITCH 36                      // 36 % 32 == 4 -> conflict-free both stages
#define GF (24 * 8 * PITCH)           // 6912 floats

// DCT-II basis b[u][i] = c(u)*cos(pi*u*(2i+1)/16); only i=0..3 needed (symmetry).
static __device__ constexpr float B4[8][4] = {
  { 0.35355339059327373f,  0.35355339059327373f,  0.35355339059327373f,  0.35355339059327373f },
  { 0.49039264020161522f,  0.41573480615127262f,  0.27778511650980114f,  0.09754516100806417f },
  { 0.46193976625564337f,  0.19134171618254492f, -0.19134171618254492f, -0.46193976625564337f },
  { 0.41573480615127262f, -0.09754516100806417f, -0.49039264020161522f, -0.27778511650980114f },
  { 0.35355339059327373f, -0.35355339059327373f, -0.35355339059327373f,  0.35355339059327373f },
  { 0.27778511650980114f, -0.49039264020161522f,  0.09754516100806417f,  0.41573480615127262f },
  { 0.19134171618254492f, -0.46193976625564337f,  0.46193976625564337f, -0.19134171618254492f },
  { 0.09754516100806417f, -0.27778511650980114f,  0.41573480615127262f, -0.49039264020161522f }
};

__global__ void __launch_bounds__(NT, 6)
dct_fused_kernel(const float* __restrict__ x,
                 const float* __restrict__ max_,
                 const float* __restrict__ min_,
                 const float* __restrict__ ycw,
                 float* __restrict__ out)
{
    __shared__ float  G[GF];          // [((c*8+u)*8 + j)*PITCH + bw]
    __shared__ float2 aff[192];

    const int t    = threadIdx.x;
    const int bx   = blockIdx.x;
    const int r    = bx >> 1;         // block-row 0..63
    const int half = bx & 1;          // 256-col half
    const int b    = blockIdx.y;

    if (t < 192) {
        const float mx = max_[b * 192 + t];
        const float mn = min_[b * 192 + t];
        const float d  = mx - mn + 1e-6f;
        const float rr = 1.0f / d;
        float r2 = rr * rr, r4 = r2 * r2, r8 = r4 * r4, r16 = r8 * r8;
        const float r32 = r16 * r16;
        aff[t] = make_float2(r32, -mn * (rr * (1.0f - r32) / (1.0f - rr)));
    }

    // ---------------- Stage A: per-channel vertical DCT (butterfly) --------
    const float* xb = x + ((size_t)b * 3 * 512 + (size_t)r * 8) * 512 + half * 256;
    const int j  = t & 7;
    const int bw = t >> 3;            // 0..31

    #pragma unroll
    for (int c = 0; c < 3; ++c) {
        float v[8];
        #pragma unroll
        for (int i = 0; i < 8; ++i)
            v[i] = __ldg(xb + c * 262144 + i * 512 + t);

        const float s0 = v[0] + v[7], s1 = v[1] + v[6], s2 = v[2] + v[5], s3 = v[3] + v[4];
        const float d0 = v[0] - v[7], d1 = v[1] - v[6], d2 = v[2] - v[5], d3 = v[3] - v[4];

        float* Gc = G + (c * 64 + j) * PITCH + bw;   // (c*8+u)*8 + j  ->  +u*8*PITCH
        #pragma unroll
        for (int u = 0; u < 8; u += 2) {
            float e = B4[u][0] * s0;
            e = fmaf(B4[u][1], s1, e);
            e = fmaf(B4[u][2], s2, e);
            e = fmaf(B4[u][3], s3, e);
            Gc[u * 8 * PITCH] = e;
            float o = B4[u + 1][0] * d0;
            o = fmaf(B4[u + 1][1], d1, o);
            o = fmaf(B4[u + 1][2], d2, o);
            o = fmaf(B4[u + 1][3], d3, o);
            Gc[(u + 1) * 8 * PITCH] = o;
        }
    }

    __syncthreads();

    // ------- Stage B: channel mix (j-domain) + horizontal DCT + affine -----
    const int bwB = t & 31;
    const int u   = t >> 5;           // 0..7
    const size_t outb = (size_t)b * 192 * 4096 + (size_t)r * 64 + half * 32 + bwB;

    #pragma unroll
    for (int q = 0; q < 3; ++q) {     // q = output (YCbCr) channel
        float m[8];
        #pragma unroll
        for (int c = 0; c < 3; ++c) { // input (RGB) channel, streamed
            const float w = ycw[q * 3 + c];
            #pragma unroll
            for (int jj = 0; jj < 8; ++jj) {
                const float g = G[((c * 8 + u) * 8 + jj) * PITCH + bwB];
                m[jj] = (c == 0) ? w * g : fmaf(w, g, m[jj]);
            }
        }

        const float s0 = m[0] + m[7], s1 = m[1] + m[6], s2 = m[2] + m[5], s3 = m[3] + m[4];
        const float d0 = m[0] - m[7], d1 = m[1] - m[6], d2 = m[2] - m[5], d3 = m[3] - m[4];

        const int kbase = q * 64 + u * 8;
        #pragma unroll
        for (int vv = 0; vv < 8; vv += 2) {
            float e = B4[vv][0] * s0;
            e = fmaf(B4[vv][1], s1, e);
            e = fmaf(B4[vv][2], s2, e);
            e = fmaf(B4[vv][3], s3, e);
            float2 sb = aff[kbase + vv];
            out[outb + (size_t)(kbase + vv) * 4096] = fmaf(e, sb.x, sb.y);

            float o = B4[vv + 1][0] * d0;
            o = fmaf(B4[vv + 1][1], d1, o);
            o = fmaf(B4[vv + 1][2], d2, o);
            o = fmaf(B4[vv + 1][3], d3, o);
            sb = aff[kbase + vv + 1];
            out[outb + (size_t)(kbase + vv + 1) * 4096] = fmaf(o, sb.x, sb.y);
        }
    }
}

extern "C" void kernel_launch(void* const* d_in, const int* in_sizes, int n_in,
                              void* d_out, int out_size)
{
    const float* x    = (const float*)d_in[0];
    const float* max_ = (const float*)d_in[1];
    const float* min_ = (const float*)d_in[2];
    const float* ycw  = (const float*)d_in[3];
    float* out = (float*)d_out;

    dim3 grid(128, 32);
    dct_fused_kernel<<<grid, NT>>>(x, max_, min_, ycw, out);
}